// round 11
// baseline (speedup 1.0000x reference)
#include <cuda_runtime.h>
#include <cuda_fp16.h>
#include <math.h>
#include <stdint.h>

#define BN    1024
#define FEATN 512
#define HN    256
#define TI    4
#define TJ    16
#define KC    64       // k per chunk (4 k16 slabs)
#define NCH   8        // 512/64
#define RSB   272      // padded A row stride bytes: 16r mod 128 -> conflict-free

// ---- smem layout (bytes from 128B-aligned dynamic base) ----
#define OFF_XI   0               // 4 x 512 f32  = 8192
#define OFF_XJ   8192            // 16 x 512 f32 = 32768
#define OFF_ST   40960           // 2 A stages x 17408
#define STAGE_SZ 17408
#define OFF_EPI  75776           // float4 per col: 256 x 16 = 4096
#define OFF_RED  79872           // 64 x 4 floats = 1024
#define SMEM_TOTAL 80896

// W1[0:512] as fp16 MMA B-fragments, per-lane order (indexed by k16 slab 0..31):
// index = sc*512 + (ng*4+nt)*32 + lane ; 16B = {tile 2t: b0,b1 | tile 2t+1: b0,b1}
__device__ uint4 g_Bf[32 * 512];

__device__ __forceinline__ uint32_t smem_u32(const void* p) {
    uint32_t a;
    asm("{ .reg .u64 t; cvta.to.shared.u64 t, %1; cvt.u32.u64 %0, t; }" : "=r"(a) : "l"(p));
    return a;
}

#define LDSM_X4(r0,r1,r2,r3,addr) \
    asm volatile("ldmatrix.sync.aligned.m8n8.x4.shared.b16 {%0,%1,%2,%3}, [%4];" \
        : "=r"(r0), "=r"(r1), "=r"(r2), "=r"(r3) : "r"(addr))

#define MMAH(d, a0,a1,a2,a3, b0,b1) \
    asm volatile("mma.sync.aligned.m16n8k16.row.col.f32.f16.f16.f32 " \
        "{%0,%1,%2,%3}, {%4,%5,%6,%7}, {%8,%9}, {%0,%1,%2,%3};" \
        : "+f"((d)[0]), "+f"((d)[1]), "+f"((d)[2]), "+f"((d)[3]) \
        : "r"(a0), "r"(a1), "r"(a2), "r"(a3), "r"(b0), "r"(b1))

// branch-free GELU: erf via A&S 7.1.26 (abs err < 1.5e-7)
__device__ __forceinline__ float gelu_erf(float x) {
    float u = 0.70710678118654752f * x;
    float a = fabsf(u);
    float den = fmaf(0.3275911f, a, 1.0f);
    float t;
    asm("rcp.approx.f32 %0, %1;" : "=f"(t) : "f"(den));
    float p = fmaf(fmaf(fmaf(fmaf(1.061405429f, t, -1.453152027f), t,
                             1.421413741f), t, -0.284496736f), t, 0.254829592f) * t;
    float e;
    asm("ex2.approx.f32 %0, %1;" : "=f"(e) : "f"(-a * a * 1.4426950408889634f));
    float erfa = fmaf(-p, e, 1.0f);
    float erfu = copysignf(erfa, u);
    return 0.5f * x * (1.0f + erfu);
}

// ---- prep: W1[0:512] -> fp16 B fragments in per-lane MMA order -------------
__global__ void prep_frag(const float* __restrict__ W1) {
    int idx  = blockIdx.x * 256 + threadIdx.x;    // 0..16383
    int lane = idx & 31;
    int tp   = (idx >> 5) & 15;
    int sc   = idx >> 9;                          // k16 slab 0..31
    int kg   = sc * 16 + (lane & 3) * 2;
    uint32_t e[4];
#pragma unroll
    for (int t2 = 0; t2 < 2; t2++) {
        int n = (tp * 2 + t2) * 8 + (lane >> 2);
        __half2 b0 = __floats2half2_rn(W1[kg * HN + n],       W1[(kg + 1) * HN + n]);
        __half2 b1 = __floats2half2_rn(W1[(kg + 8) * HN + n], W1[(kg + 9) * HN + n]);
        e[t2 * 2]     = *(uint32_t*)&b0;
        e[t2 * 2 + 1] = *(uint32_t*)&b1;
    }
    g_Bf[idx] = make_uint4(e[0], e[1], e[2], e[3]);
}

// ---- A build: |xi - xj| -> fp16, 16 k per thread, chunk of 64 k ------------
__device__ __forceinline__ void build_A(char* SB, uint32_t stg_off, int c, int tid) {
    int p  = tid >> 2;            // pair 0..63
    int kq = (tid & 3) * 16;      // k offset 0,16,32,48
    const float* xi = (const float*)(SB + OFF_XI) + (p >> 4) * 512 + c * KC + kq;
    const float* xj = (const float*)(SB + OFF_XJ) + (p & 15) * 512 + c * KC + kq;
    uint32_t hh[8];
#pragma unroll
    for (int q = 0; q < 4; q++) {
        float4 xa = *(const float4*)(xi + q * 4);
        float4 ya = *(const float4*)(xj + q * 4);
        __half2 a = __float22half2_rn(make_float2(fabsf(xa.x - ya.x), fabsf(xa.y - ya.y)));
        __half2 b = __float22half2_rn(make_float2(fabsf(xa.z - ya.z), fabsf(xa.w - ya.w)));
        hh[q * 2]     = *(uint32_t*)&a;
        hh[q * 2 + 1] = *(uint32_t*)&b;
    }
    uint32_t off = (uint32_t)(p * RSB + kq * 2);
    *(uint4*)(SB + stg_off + off)      = make_uint4(hh[0], hh[1], hh[2], hh[3]);
    *(uint4*)(SB + stg_off + off + 16) = make_uint4(hh[4], hh[5], hh[6], hh[7]);
}

// ---- main scorer: 256 thr, tile M64 x N256, 2 CTAs/SM ----------------------
__global__ __launch_bounds__(256, 2)
void scorer_mma(const float* __restrict__ X,
                const float* __restrict__ logits,
                const float* __restrict__ b1,
                const float* __restrict__ W1,
                const float* __restrict__ W2,
                const float* __restrict__ b2,
                float* __restrict__ hs)
{
    const int ib = blockIdx.y;           // 0..255 (TI=4)
    const int jb = blockIdx.x;           // 0..63  (TJ=16)
    if (jb * TJ + (TJ - 1) < ib * TI) return;

    extern __shared__ __align__(128) char SB[];
    const uint32_t sb = smem_u32(SB);

    const int tid  = threadIdx.x;
    const int wid  = tid >> 5;
    const int lane = tid & 31;
    const int i0 = ib * TI, j0 = jb * TJ;

    // 8 warps: 2 M-groups x 4 N-groups; warp covers M32 x N64
    const int mg = wid >> 2, ng = wid & 3;
    const int m0 = mg * 32, n0 = ng * 64;

    // ---- preload X rows (fp32) + epilogue constants ----
    {
        float4* dXi = (float4*)(SB + OFF_XI);
        float4* dXj = (float4*)(SB + OFF_XJ);
#pragma unroll
        for (int r = 0; r < 2; r++) {
            int idx = tid + 256 * r;              // 512 float4
            dXi[idx] = ((const float4*)X)[(i0 + (idx >> 7)) * 128 + (idx & 127)];
        }
#pragma unroll
        for (int r = 0; r < 8; r++) {
            int idx = tid + 256 * r;              // 2048 float4
            dXj[idx] = ((const float4*)X)[(j0 + (idx >> 7)) * 128 + (idx & 127)];
        }
        float4* e = (float4*)(SB + OFF_EPI);
        e[tid] = make_float4(W1[512 * HN + tid], W1[513 * HN + tid],
                             b1[tid], W2[tid]);
    }
    __syncthreads();

    build_A(SB, OFF_ST, 0, tid);

    // ---- per-thread A ldmatrix base offset ----
    const uint32_t aBase = (uint32_t)((m0 + (lane & 7) + ((lane >> 3) & 1) * 8) * RSB
                                      + ((lane >> 4) & 1) * 16);
    const uint4* __restrict__ gB = &g_Bf[ng * 128 + lane];

    float d[2][4][2][4];
#pragma unroll
    for (int a = 0; a < 2; a++)
#pragma unroll
        for (int b = 0; b < 4; b++)
#pragma unroll
            for (int cc = 0; cc < 2; cc++)
#pragma unroll
                for (int r = 0; r < 4; r++) d[a][b][cc][r] = 0.0f;

    // ---- main K loop: 8 chunks of k64 (4 k16 slabs each) ----
    for (int c = 0; c < NCH; c++) {
        const int s = c & 1;
        const uint32_t stg = sb + OFF_ST + s * STAGE_SZ;

        // B fragments for slabs 4c+0, 4c+1 — issued BEFORE the barrier so the
        // L2-hit latency drains behind the sync wait.
        uint4 Bv[8];
#pragma unroll
        for (int ks = 0; ks < 2; ks++)
#pragma unroll
            for (int nt = 0; nt < 4; nt++)
                Bv[ks * 4 + nt] = __ldg(gB + (c * 4 + ks) * 512 + nt * 32);

        __syncthreads();

        uint32_t af[2][2][4];
#pragma unroll
        for (int ks = 0; ks < 2; ks++)
#pragma unroll
            for (int m2 = 0; m2 < 2; m2++) {
                uint32_t aa = stg + aBase + m2 * (16 * RSB) + ks * 32;
                LDSM_X4(af[ks][m2][0], af[ks][m2][1], af[ks][m2][2], af[ks][m2][3], aa);
            }

        if (c + 1 < NCH)
            build_A(SB, OFF_ST + (s ^ 1) * STAGE_SZ, c + 1, tid);

#pragma unroll
        for (int ks = 0; ks < 2; ks++)
#pragma unroll
            for (int nt = 0; nt < 4; nt++)
#pragma unroll
                for (int m2 = 0; m2 < 2; m2++) {
                    MMAH(d[m2][nt][0], af[ks][m2][0],af[ks][m2][1],af[ks][m2][2],af[ks][m2][3],
                         Bv[ks*4+nt].x, Bv[ks*4+nt].y);
                    MMAH(d[m2][nt][1], af[ks][m2][0],af[ks][m2][1],af[ks][m2][2],af[ks][m2][3],
                         Bv[ks*4+nt].z, Bv[ks*4+nt].w);
                }

        // second half: slabs 4c+2, 4c+3 (LDG overlaps the burst above via
        // in-order issue; no barrier needed — same A stage)
#pragma unroll
        for (int ks = 0; ks < 2; ks++)
#pragma unroll
            for (int nt = 0; nt < 4; nt++)
                Bv[ks * 4 + nt] = __ldg(gB + (c * 4 + 2 + ks) * 512 + nt * 32);
#pragma unroll
        for (int ks = 0; ks < 2; ks++)
#pragma unroll
            for (int m2 = 0; m2 < 2; m2++) {
                uint32_t aa = stg + aBase + m2 * (16 * RSB) + (2 + ks) * 32;
                LDSM_X4(af[ks][m2][0], af[ks][m2][1], af[ks][m2][2], af[ks][m2][3], aa);
            }
#pragma unroll
        for (int ks = 0; ks < 2; ks++)
#pragma unroll
            for (int nt = 0; nt < 4; nt++)
#pragma unroll
                for (int m2 = 0; m2 < 2; m2++) {
                    MMAH(d[m2][nt][0], af[ks][m2][0],af[ks][m2][1],af[ks][m2][2],af[ks][m2][3],
                         Bv[ks*4+nt].x, Bv[ks*4+nt].y);
                    MMAH(d[m2][nt][1], af[ks][m2][0],af[ks][m2][1],af[ks][m2][2],af[ks][m2][3],
                         Bv[ks*4+nt].z, Bv[ks*4+nt].w);
                }
    }
    __syncthreads();

    // ---- epilogue ----
    float c0[4], c1[4], sacc[4];
#pragma unroll
    for (int rr = 0; rr < 4; rr++) {
        int p = m0 + (lane >> 2) + 8 * rr;
        int gi = i0 + (p >> 4), gj = j0 + (p & 15);
        float pi = 1.0f / (1.0f + expf(logits[gi*2+1] - logits[gi*2]));
        float pj = 1.0f / (1.0f + expf(logits[gj*2+1] - logits[gj*2]));
        c0[rr] = pi * pj;
        c1[rr] = (1.0f - pi) * (1.0f - pj);
        sacc[rr] = 0.0f;
    }

    const float4* epi4 = (const float4*)(SB + OFF_EPI);
#pragma unroll
    for (int nt = 0; nt < 4; nt++)
#pragma unroll
        for (int half = 0; half < 2; half++)
#pragma unroll
            for (int e = 0; e < 2; e++) {
                int col = n0 + nt * 16 + half * 8 + (lane & 3) * 2 + e;
                float4 w = epi4[col];
#pragma unroll
                for (int rr = 0; rr < 4; rr++) {
                    int m2 = rr >> 1;
                    int idx = (rr & 1) * 2 + e;
                    float x = d[m2][nt][half][idx]
                            + c0[rr] * w.x + c1[rr] * w.y + w.z;
                    sacc[rr] = fmaf(gelu_erf(x), w.w, sacc[rr]);
                }
            }

#pragma unroll
    for (int rr = 0; rr < 4; rr++) {
        sacc[rr] += __shfl_xor_sync(0xffffffffu, sacc[rr], 1);
        sacc[rr] += __shfl_xor_sync(0xffffffffu, sacc[rr], 2);
    }
    float* red = (float*)(SB + OFF_RED);
    if ((lane & 3) == 0) {
#pragma unroll
        for (int rr = 0; rr < 4; rr++) {
            int p = m0 + (lane >> 2) + 8 * rr;
            red[p * 4 + ng] = sacc[rr];
        }
    }
    __syncthreads();

    if (tid < 64) {
        int p = tid;
        float4 r4 = *(const float4*)&red[p * 4];
        float tot = (r4.x + r4.y) + (r4.z + r4.w) + b2[0];
        float sc = 1.0f / (1.0f + expf(-tot));
        int gi = i0 + (p >> 4), gj = j0 + (p & 15);
        hs[gi * BN + gj] = sc;
        hs[gj * BN + gi] = sc;
    }
}

// ---------------- row softmax of adj + 5*log(hs + 1e-8) ----------------
__global__ __launch_bounds__(256)
void softmax_kernel(const float* __restrict__ adj,
                    const float* __restrict__ hs,
                    float* __restrict__ out)
{
    const int row = blockIdx.x;
    const int tid = threadIdx.x;
    __shared__ float red[256];

    float v[4];
    float mx = -3.4e38f;
#pragma unroll
    for (int u = 0; u < 4; u++) {
        int j = tid + 256 * u;
        float s = hs[row * BN + j];
        v[u] = adj[row * BN + j] + 5.0f * logf(s + 1e-8f);
        mx = fmaxf(mx, v[u]);
    }
    red[tid] = mx;
    __syncthreads();
    for (int off = 128; off > 0; off >>= 1) {
        if (tid < off) red[tid] = fmaxf(red[tid], red[tid + off]);
        __syncthreads();
    }
    mx = red[0];
    __syncthreads();

    float sum = 0.0f;
#pragma unroll
    for (int u = 0; u < 4; u++) {
        v[u] = expf(v[u] - mx);
        sum += v[u];
    }
    red[tid] = sum;
    __syncthreads();
    for (int off = 128; off > 0; off >>= 1) {
        if (tid < off) red[tid] += red[tid + off];
        __syncthreads();
    }
    float inv = 1.0f / red[0];
#pragma unroll
    for (int u = 0; u < 4; u++) {
        int j = tid + 256 * u;
        out[row * BN + j] = v[u] * inv;
    }
}

extern "C" void kernel_launch(void* const* d_in, const int* in_sizes, int n_in,
                              void* d_out, int out_size)
{
    const float* X      = (const float*)d_in[0];   // [1024, 512]
    const float* logits = (const float*)d_in[1];   // [1024, 2]
    const float* adj    = (const float*)d_in[2];   // [1024, 1024]
    const float* W1     = (const float*)d_in[3];   // [514, 256]
    const float* b1     = (const float*)d_in[4];   // [256]
    const float* W2     = (const float*)d_in[5];   // [256, 1]
    const float* b2     = (const float*)d_in[6];   // [1]

    float* out = (float*)d_out;          // [adj_refined (1M) | h_scores (1M)]
    float* hs  = out + BN * BN;

    static int configured = 0;
    if (!configured) {
        cudaFuncSetAttribute(scorer_mma, cudaFuncAttributeMaxDynamicSharedMemorySize, SMEM_TOTAL);
        configured = 1;
    }

    prep_frag<<<64, 256>>>(W1);
    dim3 grid(BN / TJ, BN / TI);   // (64, 256)
    scorer_mma<<<grid, 256, SMEM_TOTAL>>>(X, logits, b1, W1, W2, b2, hs);
    softmax_kernel<<<BN, 256>>>(adj, hs, out);
}

// round 12
// speedup vs baseline: 1.3443x; 1.3443x over previous
#include <cuda_runtime.h>
#include <cuda_fp16.h>
#include <math.h>
#include <stdint.h>

#define BN    1024
#define FEATN 512
#define HN    256
#define TI    4
#define TJ    16
#define KC    32       // k per chunk (2 k16 slabs)
#define NCH   16       // 512/32
#define RSB   80       // padded A row stride bytes: conflict-free ldmatrix

// ---- smem layout (bytes from 128B-aligned dynamic base) ----
#define OFF_XI   0               // 4 x 512 f32  = 8192
#define OFF_XJ   8192            // 16 x 512 f32 = 32768
#define OFF_ST   40960           // 2 A stages x 5120
#define STAGE_SZ 5120
#define OFF_EPI  51200           // float4 per col: 256 x 16 = 4096
#define OFF_RED  55296           // 64 x 4 floats = 1024
#define SMEM_TOTAL 56320

// W1[0:512] as fp16 MMA B-fragments, per-lane order (indexed by k16 slab 0..31):
// index = sc*512 + (ng*4+nt)*32 + lane ; 16B = {tile 2t: b0,b1 | tile 2t+1: b0,b1}
__device__ uint4 g_Bf[32 * 512];

__device__ __forceinline__ uint32_t smem_u32(const void* p) {
    uint32_t a;
    asm("{ .reg .u64 t; cvta.to.shared.u64 t, %1; cvt.u32.u64 %0, t; }" : "=r"(a) : "l"(p));
    return a;
}

#define LDSM_X4(r0,r1,r2,r3,addr) \
    asm volatile("ldmatrix.sync.aligned.m8n8.x4.shared.b16 {%0,%1,%2,%3}, [%4];" \
        : "=r"(r0), "=r"(r1), "=r"(r2), "=r"(r3) : "r"(addr))

#define MMAH(d, a0,a1,a2,a3, b0,b1) \
    asm volatile("mma.sync.aligned.m16n8k16.row.col.f32.f16.f16.f32 " \
        "{%0,%1,%2,%3}, {%4,%5,%6,%7}, {%8,%9}, {%0,%1,%2,%3};" \
        : "+f"((d)[0]), "+f"((d)[1]), "+f"((d)[2]), "+f"((d)[3]) \
        : "r"(a0), "r"(a1), "r"(a2), "r"(a3), "r"(b0), "r"(b1))

// branch-free GELU: erf via A&S 7.1.26 (abs err < 1.5e-7)
__device__ __forceinline__ float gelu_erf(float x) {
    float u = 0.70710678118654752f * x;
    float a = fabsf(u);
    float den = fmaf(0.3275911f, a, 1.0f);
    float t;
    asm("rcp.approx.f32 %0, %1;" : "=f"(t) : "f"(den));
    float p = fmaf(fmaf(fmaf(fmaf(1.061405429f, t, -1.453152027f), t,
                             1.421413741f), t, -0.284496736f), t, 0.254829592f) * t;
    float e;
    asm("ex2.approx.f32 %0, %1;" : "=f"(e) : "f"(-a * a * 1.4426950408889634f));
    float erfa = fmaf(-p, e, 1.0f);
    float erfu = copysignf(erfa, u);
    return 0.5f * x * (1.0f + erfu);
}

// ---- prep: W1[0:512] -> fp16 B fragments in per-lane MMA order -------------
__global__ void prep_frag(const float* __restrict__ W1) {
    int idx  = blockIdx.x * 256 + threadIdx.x;    // 0..16383
    int lane = idx & 31;
    int tp   = (idx >> 5) & 15;
    int sc   = idx >> 9;                          // k16 slab 0..31
    int kg   = sc * 16 + (lane & 3) * 2;
    uint32_t e[4];
#pragma unroll
    for (int t2 = 0; t2 < 2; t2++) {
        int n = (tp * 2 + t2) * 8 + (lane >> 2);
        __half2 b0 = __floats2half2_rn(W1[kg * HN + n],       W1[(kg + 1) * HN + n]);
        __half2 b1 = __floats2half2_rn(W1[(kg + 8) * HN + n], W1[(kg + 9) * HN + n]);
        e[t2 * 2]     = *(uint32_t*)&b0;
        e[t2 * 2 + 1] = *(uint32_t*)&b1;
    }
    g_Bf[idx] = make_uint4(e[0], e[1], e[2], e[3]);
}

// ---- A build: |xi - xj| -> fp16, 8 k per thread, chunk of 32 k -------------
__device__ __forceinline__ void build_A(char* SB, uint32_t stg_off, int c, int tid) {
    int p  = tid >> 2;            // pair 0..63
    int kq = (tid & 3) * 8;       // k offset 0,8,16,24
    const float* xi = (const float*)(SB + OFF_XI) + (p >> 4) * 512 + c * KC + kq;
    const float* xj = (const float*)(SB + OFF_XJ) + (p & 15) * 512 + c * KC + kq;
    float4 xa = *(const float4*)xi, xb = *(const float4*)(xi + 4);
    float4 ya = *(const float4*)xj, yb = *(const float4*)(xj + 4);
    __half2 h0 = __float22half2_rn(make_float2(fabsf(xa.x - ya.x), fabsf(xa.y - ya.y)));
    __half2 h1 = __float22half2_rn(make_float2(fabsf(xa.z - ya.z), fabsf(xa.w - ya.w)));
    __half2 h2 = __float22half2_rn(make_float2(fabsf(xb.x - yb.x), fabsf(xb.y - yb.y)));
    __half2 h3 = __float22half2_rn(make_float2(fabsf(xb.z - yb.z), fabsf(xb.w - yb.w)));
    uint32_t off = (uint32_t)(p * RSB + kq * 2);
    *(uint4*)(SB + stg_off + off) = make_uint4(*(uint32_t*)&h0, *(uint32_t*)&h1,
                                               *(uint32_t*)&h2, *(uint32_t*)&h3);
}

// ---- main scorer: 256 thr, tile M64 x N256, 2 CTAs/SM ----------------------
__global__ __launch_bounds__(256, 2)
void scorer_mma(const float* __restrict__ X,
                const float* __restrict__ logits,
                const float* __restrict__ b1,
                const float* __restrict__ W1,
                const float* __restrict__ W2,
                const float* __restrict__ b2,
                float* __restrict__ hs)
{
    const int ib = blockIdx.y;           // 0..255 (TI=4)
    const int jb = blockIdx.x;           // 0..63  (TJ=16)
    if (jb * TJ + (TJ - 1) < ib * TI) return;

    extern __shared__ __align__(128) char SB[];
    const uint32_t sb = smem_u32(SB);

    const int tid  = threadIdx.x;
    const int wid  = tid >> 5;
    const int lane = tid & 31;
    const int i0 = ib * TI, j0 = jb * TJ;

    // 8 warps: 2 M-groups x 4 N-groups; warp covers M32 x N64
    const int mg = wid >> 2, ng = wid & 3;
    const int m0 = mg * 32, n0 = ng * 64;

    // ---- preload X rows (fp32) + epilogue constants ----
    {
        float4* dXi = (float4*)(SB + OFF_XI);
        float4* dXj = (float4*)(SB + OFF_XJ);
#pragma unroll
        for (int r = 0; r < 2; r++) {
            int idx = tid + 256 * r;              // 512 float4
            dXi[idx] = ((const float4*)X)[(i0 + (idx >> 7)) * 128 + (idx & 127)];
        }
#pragma unroll
        for (int r = 0; r < 8; r++) {
            int idx = tid + 256 * r;              // 2048 float4
            dXj[idx] = ((const float4*)X)[(j0 + (idx >> 7)) * 128 + (idx & 127)];
        }
        float4* e = (float4*)(SB + OFF_EPI);
        e[tid] = make_float4(W1[512 * HN + tid], W1[513 * HN + tid],
                             b1[tid], W2[tid]);
    }
    __syncthreads();

    build_A(SB, OFF_ST, 0, tid);

    // ---- per-thread A ldmatrix base offset ----
    const uint32_t aBase = (uint32_t)((m0 + (lane & 7) + ((lane >> 3) & 1) * 8) * RSB
                                      + ((lane >> 4) & 1) * 16);
    const uint4* __restrict__ gB = &g_Bf[ng * 128 + lane];

    float d[2][4][2][4];
#pragma unroll
    for (int a = 0; a < 2; a++)
#pragma unroll
        for (int b = 0; b < 4; b++)
#pragma unroll
            for (int cc = 0; cc < 2; cc++)
#pragma unroll
                for (int r = 0; r < 4; r++) d[a][b][cc][r] = 0.0f;

    // ---- main K loop: 16 chunks of k32 ----
    for (int c = 0; c < NCH; c++) {
        const int s = c & 1;
        const uint32_t stg = sb + OFF_ST + s * STAGE_SZ;

        // slab 0 B fragments issued BEFORE the barrier: L2 latency drains
        // behind the bar.sync wait (only 16 extra live regs across barrier)
        uint4 Bv0[4];
#pragma unroll
        for (int nt = 0; nt < 4; nt++)
            Bv0[nt] = __ldg(gB + (c * 2) * 512 + nt * 32);

        __syncthreads();

        uint32_t af[2][2][4];
#pragma unroll
        for (int ks = 0; ks < 2; ks++)
#pragma unroll
            for (int m2 = 0; m2 < 2; m2++) {
                uint32_t aa = stg + aBase + m2 * (16 * RSB) + ks * 32;
                LDSM_X4(af[ks][m2][0], af[ks][m2][1], af[ks][m2][2], af[ks][m2][3], aa);
            }

        // slab 1 B fragments: overlap the slab-0 MMA burst below
        uint4 Bv1[4];
#pragma unroll
        for (int nt = 0; nt < 4; nt++)
            Bv1[nt] = __ldg(gB + (c * 2 + 1) * 512 + nt * 32);

        if (c + 1 < NCH)
            build_A(SB, OFF_ST + (s ^ 1) * STAGE_SZ, c + 1, tid);

#pragma unroll
        for (int nt = 0; nt < 4; nt++)
#pragma unroll
            for (int m2 = 0; m2 < 2; m2++) {
                MMAH(d[m2][nt][0], af[0][m2][0],af[0][m2][1],af[0][m2][2],af[0][m2][3],
                     Bv0[nt].x, Bv0[nt].y);
                MMAH(d[m2][nt][1], af[0][m2][0],af[0][m2][1],af[0][m2][2],af[0][m2][3],
                     Bv0[nt].z, Bv0[nt].w);
            }
#pragma unroll
        for (int nt = 0; nt < 4; nt++)
#pragma unroll
            for (int m2 = 0; m2 < 2; m2++) {
                MMAH(d[m2][nt][0], af[1][m2][0],af[1][m2][1],af[1][m2][2],af[1][m2][3],
                     Bv1[nt].x, Bv1[nt].y);
                MMAH(d[m2][nt][1], af[1][m2][0],af[1][m2][1],af[1][m2][2],af[1][m2][3],
                     Bv1[nt].z, Bv1[nt].w);
            }
    }
    __syncthreads();

    // ---- epilogue ----
    float c0[4], c1[4], sacc[4];
#pragma unroll
    for (int rr = 0; rr < 4; rr++) {
        int p = m0 + (lane >> 2) + 8 * rr;
        int gi = i0 + (p >> 4), gj = j0 + (p & 15);
        float pi = 1.0f / (1.0f + expf(logits[gi*2+1] - logits[gi*2]));
        float pj = 1.0f / (1.0f + expf(logits[gj*2+1] - logits[gj*2]));
        c0[rr] = pi * pj;
        c1[rr] = (1.0f - pi) * (1.0f - pj);
        sacc[rr] = 0.0f;
    }

    const float4* epi4 = (const float4*)(SB + OFF_EPI);
#pragma unroll
    for (int nt = 0; nt < 4; nt++)
#pragma unroll
        for (int half = 0; half < 2; half++)
#pragma unroll
            for (int e = 0; e < 2; e++) {
                int col = n0 + nt * 16 + half * 8 + (lane & 3) * 2 + e;
                float4 w = epi4[col];
#pragma unroll
                for (int rr = 0; rr < 4; rr++) {
                    int m2 = rr >> 1;
                    int idx = (rr & 1) * 2 + e;
                    float x = d[m2][nt][half][idx]
                            + c0[rr] * w.x + c1[rr] * w.y + w.z;
                    sacc[rr] = fmaf(gelu_erf(x), w.w, sacc[rr]);
                }
            }

#pragma unroll
    for (int rr = 0; rr < 4; rr++) {
        sacc[rr] += __shfl_xor_sync(0xffffffffu, sacc[rr], 1);
        sacc[rr] += __shfl_xor_sync(0xffffffffu, sacc[rr], 2);
    }
    float* red = (float*)(SB + OFF_RED);
    if ((lane & 3) == 0) {
#pragma unroll
        for (int rr = 0; rr < 4; rr++) {
            int p = m0 + (lane >> 2) + 8 * rr;
            red[p * 4 + ng] = sacc[rr];
        }
    }
    __syncthreads();

    if (tid < 64) {
        int p = tid;
        float4 r4 = *(const float4*)&red[p * 4];
        float tot = (r4.x + r4.y) + (r4.z + r4.w) + b2[0];
        float sc = 1.0f / (1.0f + expf(-tot));
        int gi = i0 + (p >> 4), gj = j0 + (p & 15);
        hs[gi * BN + gj] = sc;
        hs[gj * BN + gi] = sc;
    }
}

// ---------------- row softmax of adj + 5*log(hs + 1e-8) ----------------
__global__ __launch_bounds__(256)
void softmax_kernel(const float* __restrict__ adj,
                    const float* __restrict__ hs,
                    float* __restrict__ out)
{
    const int row = blockIdx.x;
    const int tid = threadIdx.x;
    __shared__ float red[256];

    float v[4];
    float mx = -3.4e38f;
#pragma unroll
    for (int u = 0; u < 4; u++) {
        int j = tid + 256 * u;
        float s = hs[row * BN + j];
        v[u] = adj[row * BN + j] + 5.0f * logf(s + 1e-8f);
        mx = fmaxf(mx, v[u]);
    }
    red[tid] = mx;
    __syncthreads();
    for (int off = 128; off > 0; off >>= 1) {
        if (tid < off) red[tid] = fmaxf(red[tid], red[tid + off]);
        __syncthreads();
    }
    mx = red[0];
    __syncthreads();

    float sum = 0.0f;
#pragma unroll
    for (int u = 0; u < 4; u++) {
        v[u] = expf(v[u] - mx);
        sum += v[u];
    }
    red[tid] = sum;
    __syncthreads();
    for (int off = 128; off > 0; off >>= 1) {
        if (tid < off) red[tid] += red[tid + off];
        __syncthreads();
    }
    float inv = 1.0f / red[0];
#pragma unroll
    for (int u = 0; u < 4; u++) {
        int j = tid + 256 * u;
        out[row * BN + j] = v[u] * inv;
    }
}

extern "C" void kernel_launch(void* const* d_in, const int* in_sizes, int n_in,
                              void* d_out, int out_size)
{
    const float* X      = (const float*)d_in[0];   // [1024, 512]
    const float* logits = (const float*)d_in[1];   // [1024, 2]
    const float* adj    = (const float*)d_in[2];   // [1024, 1024]
    const float* W1     = (const float*)d_in[3];   // [514, 256]
    const float* b1     = (const float*)d_in[4];   // [256]
    const float* W2     = (const float*)d_in[5];   // [256, 1]
    const float* b2     = (const float*)d_in[6];   // [1]

    float* out = (float*)d_out;          // [adj_refined (1M) | h_scores (1M)]
    float* hs  = out + BN * BN;

    static int configured = 0;
    if (!configured) {
        cudaFuncSetAttribute(scorer_mma, cudaFuncAttributeMaxDynamicSharedMemorySize, SMEM_TOTAL);
        configured = 1;
    }

    prep_frag<<<64, 256>>>(W1);
    dim3 grid(BN / TJ, BN / TI);   // (64, 256)
    scorer_mma<<<grid, 256, SMEM_TOTAL>>>(X, logits, b1, W1, W2, b2, hs);
    softmax_kernel<<<BN, 256>>>(adj, hs, out);
}

// round 13
// speedup vs baseline: 1.4393x; 1.0707x over previous
#include <cuda_runtime.h>
#include <cuda_fp16.h>
#include <math.h>
#include <stdint.h>

#define BN    1024
#define FEATN 512
#define HN    256
#define TI    4
#define TJ    16
#define KC    32       // k per chunk (2 k16 slabs)
#define NCH   16       // 512/32
#define RSB   80       // padded A row stride bytes: conflict-free ldmatrix
#define IBG   2        // i-subtiles per CTA

// ---- smem layout (bytes from 128B-aligned dynamic base) ----
#define OFF_XI   0               // 4 x 512 f32  = 8192
#define OFF_XJ   8192            // 16 x 512 f32 = 32768
#define OFF_ST   40960           // 2 A stages x 5120
#define STAGE_SZ 5120
#define OFF_EPI  51200           // float4 per col: 256 x 16 = 4096
#define OFF_RED  55296           // 64 x 4 floats = 1024
#define SMEM_TOTAL 56320

// W1[0:512] as fp16 MMA B-fragments, per-lane order (indexed by k16 slab 0..31):
// index = sc*512 + (ng*4+nt)*32 + lane ; 16B = {tile 2t: b0,b1 | tile 2t+1: b0,b1}
__device__ uint4 g_Bf[32 * 512];

__device__ __forceinline__ uint32_t smem_u32(const void* p) {
    uint32_t a;
    asm("{ .reg .u64 t; cvta.to.shared.u64 t, %1; cvt.u32.u64 %0, t; }" : "=r"(a) : "l"(p));
    return a;
}

#define LDSM_X4(r0,r1,r2,r3,addr) \
    asm volatile("ldmatrix.sync.aligned.m8n8.x4.shared.b16 {%0,%1,%2,%3}, [%4];" \
        : "=r"(r0), "=r"(r1), "=r"(r2), "=r"(r3) : "r"(addr))

#define MMAH(d, a0,a1,a2,a3, b0,b1) \
    asm volatile("mma.sync.aligned.m16n8k16.row.col.f32.f16.f16.f32 " \
        "{%0,%1,%2,%3}, {%4,%5,%6,%7}, {%8,%9}, {%0,%1,%2,%3};" \
        : "+f"((d)[0]), "+f"((d)[1]), "+f"((d)[2]), "+f"((d)[3]) \
        : "r"(a0), "r"(a1), "r"(a2), "r"(a3), "r"(b0), "r"(b1))

__device__ __forceinline__ float fast_ex2(float x) {
    float e;
    asm("ex2.approx.f32 %0, %1;" : "=f"(e) : "f"(x));
    return e;
}
__device__ __forceinline__ float fast_rcp(float x) {
    float r;
    asm("rcp.approx.f32 %0, %1;" : "=f"(r) : "f"(x));
    return r;
}
// fast sigmoid(x) = 1/(1+2^(-x*log2e))
__device__ __forceinline__ float fast_sigmoid(float x) {
    return fast_rcp(1.0f + fast_ex2(-1.4426950408889634f * x));
}

// branch-free GELU: erf via A&S 7.1.25 3-term (abs err < 2.5e-5)
__device__ __forceinline__ float gelu_erf(float x) {
    float u = 0.70710678118654752f * x;
    float a = fabsf(u);
    float t = fast_rcp(fmaf(0.47047f, a, 1.0f));
    float p = fmaf(fmaf(0.7478556f, t, -0.0958798f), t, 0.3480242f) * t;
    float e = fast_ex2(a * a * -1.4426950408889634f);
    float erfa = fmaf(-p, e, 1.0f);
    float erfu = copysignf(erfa, u);
    return 0.5f * x * (1.0f + erfu);
}

// ---- prep: W1[0:512] -> fp16 B fragments in per-lane MMA order -------------
__global__ void prep_frag(const float* __restrict__ W1) {
    int idx  = blockIdx.x * 256 + threadIdx.x;    // 0..16383
    int lane = idx & 31;
    int tp   = (idx >> 5) & 15;
    int sc   = idx >> 9;                          // k16 slab 0..31
    int kg   = sc * 16 + (lane & 3) * 2;
    uint32_t e[4];
#pragma unroll
    for (int t2 = 0; t2 < 2; t2++) {
        int n = (tp * 2 + t2) * 8 + (lane >> 2);
        __half2 b0 = __floats2half2_rn(W1[kg * HN + n],       W1[(kg + 1) * HN + n]);
        __half2 b1 = __floats2half2_rn(W1[(kg + 8) * HN + n], W1[(kg + 9) * HN + n]);
        e[t2 * 2]     = *(uint32_t*)&b0;
        e[t2 * 2 + 1] = *(uint32_t*)&b1;
    }
    g_Bf[idx] = make_uint4(e[0], e[1], e[2], e[3]);
}

// ---- A build: |xi - xj| -> fp16, 8 k per thread, chunk of 32 k -------------
__device__ __forceinline__ void build_A(char* SB, uint32_t stg_off, int c, int tid) {
    int p  = tid >> 2;            // pair 0..63
    int kq = (tid & 3) * 8;       // k offset 0,8,16,24
    const float* xi = (const float*)(SB + OFF_XI) + (p >> 4) * 512 + c * KC + kq;
    const float* xj = (const float*)(SB + OFF_XJ) + (p & 15) * 512 + c * KC + kq;
    float4 xa = *(const float4*)xi, xb = *(const float4*)(xi + 4);
    float4 ya = *(const float4*)xj, yb = *(const float4*)(xj + 4);
    __half2 h0 = __float22half2_rn(make_float2(fabsf(xa.x - ya.x), fabsf(xa.y - ya.y)));
    __half2 h1 = __float22half2_rn(make_float2(fabsf(xa.z - ya.z), fabsf(xa.w - ya.w)));
    __half2 h2 = __float22half2_rn(make_float2(fabsf(xb.x - yb.x), fabsf(xb.y - yb.y)));
    __half2 h3 = __float22half2_rn(make_float2(fabsf(xb.z - yb.z), fabsf(xb.w - yb.w)));
    uint32_t off = (uint32_t)(p * RSB + kq * 2);
    *(uint4*)(SB + stg_off + off) = make_uint4(*(uint32_t*)&h0, *(uint32_t*)&h1,
                                               *(uint32_t*)&h2, *(uint32_t*)&h3);
}

// ---- main scorer: 256 thr, 2 x (M64 x N256) subtiles per CTA, 2 CTAs/SM ----
__global__ __launch_bounds__(256, 2)
void scorer_mma(const float* __restrict__ X,
                const float* __restrict__ logits,
                const float* __restrict__ b1,
                const float* __restrict__ W1,
                const float* __restrict__ W2,
                const float* __restrict__ b2,
                float* __restrict__ hs)
{
    const int ibp = blockIdx.y;          // 0..127 (pairs of TI=4 tiles)
    const int jb  = blockIdx.x;          // 0..63  (TJ=16)
    if (jb * TJ + (TJ - 1) < ibp * IBG * TI) return;   // both subtiles below diag

    extern __shared__ __align__(128) char SB[];
    const uint32_t sb = smem_u32(SB);

    const int tid  = threadIdx.x;
    const int wid  = tid >> 5;
    const int lane = tid & 31;
    const int j0 = jb * TJ;

    // 8 warps: 2 M-groups x 4 N-groups; warp covers M32 x N64
    const int mg = wid >> 2, ng = wid & 3;
    const int m0 = mg * 32, n0 = ng * 64;

    // ---- preload Xj rows (once) + epilogue constants (once) ----
    {
        float4* dXj = (float4*)(SB + OFF_XJ);
#pragma unroll
        for (int r = 0; r < 8; r++) {
            int idx = tid + 256 * r;              // 2048 float4
            dXj[idx] = ((const float4*)X)[(j0 + (idx >> 7)) * 128 + (idx & 127)];
        }
        float4* e = (float4*)(SB + OFF_EPI);
        e[tid] = make_float4(W1[512 * HN + tid], W1[513 * HN + tid],
                             b1[tid], W2[tid]);
    }

    // ---- per-thread A ldmatrix base offset / B pointer ----
    const uint32_t aBase = (uint32_t)((m0 + (lane & 7) + ((lane >> 3) & 1) * 8) * RSB
                                      + ((lane >> 4) & 1) * 16);
    const uint4* __restrict__ gB = &g_Bf[ng * 128 + lane];
    const float b2w = b2[0];

#pragma unroll 1
    for (int g = 0; g < IBG; g++) {
        const int ib = ibp * IBG + g;
        if (jb * TJ + (TJ - 1) < ib * TI) continue;
        const int i0 = ib * TI;

        // ---- load Xi rows for this subtile ----
        {
            float4* dXi = (float4*)(SB + OFF_XI);
#pragma unroll
            for (int r = 0; r < 2; r++) {
                int idx = tid + 256 * r;          // 512 float4
                dXi[idx] = ((const float4*)X)[(i0 + (idx >> 7)) * 128 + (idx & 127)];
            }
        }
        __syncthreads();

        build_A(SB, OFF_ST, 0, tid);

        float d[2][4][2][4];
#pragma unroll
        for (int a = 0; a < 2; a++)
#pragma unroll
            for (int b = 0; b < 4; b++)
#pragma unroll
                for (int cc = 0; cc < 2; cc++)
#pragma unroll
                    for (int r = 0; r < 4; r++) d[a][b][cc][r] = 0.0f;

        // ---- main K loop: 16 chunks of k32 ----
        for (int c = 0; c < NCH; c++) {
            const int s = c & 1;
            const uint32_t stg = sb + OFF_ST + s * STAGE_SZ;

            uint4 Bv0[4];
#pragma unroll
            for (int nt = 0; nt < 4; nt++)
                Bv0[nt] = __ldg(gB + (c * 2) * 512 + nt * 32);

            __syncthreads();

            uint32_t af[2][2][4];
#pragma unroll
            for (int ks = 0; ks < 2; ks++)
#pragma unroll
                for (int m2 = 0; m2 < 2; m2++) {
                    uint32_t aa = stg + aBase + m2 * (16 * RSB) + ks * 32;
                    LDSM_X4(af[ks][m2][0], af[ks][m2][1], af[ks][m2][2], af[ks][m2][3], aa);
                }

            uint4 Bv1[4];
#pragma unroll
            for (int nt = 0; nt < 4; nt++)
                Bv1[nt] = __ldg(gB + (c * 2 + 1) * 512 + nt * 32);

            if (c + 1 < NCH)
                build_A(SB, OFF_ST + (s ^ 1) * STAGE_SZ, c + 1, tid);

#pragma unroll
            for (int nt = 0; nt < 4; nt++)
#pragma unroll
                for (int m2 = 0; m2 < 2; m2++) {
                    MMAH(d[m2][nt][0], af[0][m2][0],af[0][m2][1],af[0][m2][2],af[0][m2][3],
                         Bv0[nt].x, Bv0[nt].y);
                    MMAH(d[m2][nt][1], af[0][m2][0],af[0][m2][1],af[0][m2][2],af[0][m2][3],
                         Bv0[nt].z, Bv0[nt].w);
                }
#pragma unroll
            for (int nt = 0; nt < 4; nt++)
#pragma unroll
                for (int m2 = 0; m2 < 2; m2++) {
                    MMAH(d[m2][nt][0], af[1][m2][0],af[1][m2][1],af[1][m2][2],af[1][m2][3],
                         Bv1[nt].x, Bv1[nt].y);
                    MMAH(d[m2][nt][1], af[1][m2][0],af[1][m2][1],af[1][m2][2],af[1][m2][3],
                         Bv1[nt].z, Bv1[nt].w);
                }
        }
        __syncthreads();

        // ---- epilogue ----
        float c0[4], c1[4], sacc[4];
#pragma unroll
        for (int rr = 0; rr < 4; rr++) {
            int p = m0 + (lane >> 2) + 8 * rr;
            int gi = i0 + (p >> 4), gj = j0 + (p & 15);
            float pi = fast_sigmoid(logits[gi*2] - logits[gi*2+1]);
            float pj = fast_sigmoid(logits[gj*2] - logits[gj*2+1]);
            c0[rr] = pi * pj;
            c1[rr] = (1.0f - pi) * (1.0f - pj);
            sacc[rr] = 0.0f;
        }

        const float4* epi4 = (const float4*)(SB + OFF_EPI);
#pragma unroll
        for (int nt = 0; nt < 4; nt++)
#pragma unroll
            for (int half = 0; half < 2; half++)
#pragma unroll
                for (int e = 0; e < 2; e++) {
                    int col = n0 + nt * 16 + half * 8 + (lane & 3) * 2 + e;
                    float4 w = epi4[col];
#pragma unroll
                    for (int rr = 0; rr < 4; rr++) {
                        int m2 = rr >> 1;
                        int idx = (rr & 1) * 2 + e;
                        float x = d[m2][nt][half][idx]
                                + c0[rr] * w.x + c1[rr] * w.y + w.z;
                        sacc[rr] = fmaf(gelu_erf(x), w.w, sacc[rr]);
                    }
                }

#pragma unroll
        for (int rr = 0; rr < 4; rr++) {
            sacc[rr] += __shfl_xor_sync(0xffffffffu, sacc[rr], 1);
            sacc[rr] += __shfl_xor_sync(0xffffffffu, sacc[rr], 2);
        }
        float* red = (float*)(SB + OFF_RED);
        if ((lane & 3) == 0) {
#pragma unroll
            for (int rr = 0; rr < 4; rr++) {
                int p = m0 + (lane >> 2) + 8 * rr;
                red[p * 4 + ng] = sacc[rr];
            }
        }
        __syncthreads();

        if (tid < 64) {
            int p = tid;
            float4 r4 = *(const float4*)&red[p * 4];
            float tot = (r4.x + r4.y) + (r4.z + r4.w) + b2w;
            float sc = fast_sigmoid(tot);
            int gi = i0 + (p >> 4), gj = j0 + (p & 15);
            hs[gi * BN + gj] = sc;
            hs[gj * BN + gi] = sc;
        }
        __syncthreads();   // red/Xi safe for next subtile
    }
}

// ---------------- row softmax of adj + 5*log(hs + 1e-8) ----------------
__global__ __launch_bounds__(256)
void softmax_kernel(const float* __restrict__ adj,
                    const float* __restrict__ hs,
                    float* __restrict__ out)
{
    const int row = blockIdx.x;
    const int tid = threadIdx.x;
    __shared__ float red[256];

    float v[4];
    float mx = -3.4e38f;
#pragma unroll
    for (int u = 0; u < 4; u++) {
        int j = tid + 256 * u;
        float s = hs[row * BN + j];
        v[u] = adj[row * BN + j] + 5.0f * __logf(s + 1e-8f);
        mx = fmaxf(mx, v[u]);
    }
    red[tid] = mx;
    __syncthreads();
    for (int off = 128; off > 0; off >>= 1) {
        if (tid < off) red[tid] = fmaxf(red[tid], red[tid + off]);
        __syncthreads();
    }
    mx = red[0];
    __syncthreads();

    float sum = 0.0f;
#pragma unroll
    for (int u = 0; u < 4; u++) {
        v[u] = __expf(v[u] - mx);
        sum += v[u];
    }
    red[tid] = sum;
    __syncthreads();
    for (int off = 128; off > 0; off >>= 1) {
        if (tid < off) red[tid] += red[tid + off];
        __syncthreads();
    }
    float inv = 1.0f / red[0];
#pragma unroll
    for (int u = 0; u < 4; u++) {
        int j = tid + 256 * u;
        out[row * BN + j] = v[u] * inv;
    }
}

extern "C" void kernel_launch(void* const* d_in, const int* in_sizes, int n_in,
                              void* d_out, int out_size)
{
    const float* X      = (const float*)d_in[0];   // [1024, 512]
    const float* logits = (const float*)d_in[1];   // [1024, 2]
    const float* adj    = (const float*)d_in[2];   // [1024, 1024]
    const float* W1     = (const float*)d_in[3];   // [514, 256]
    const float* b1     = (const float*)d_in[4];   // [256]
    const float* W2     = (const float*)d_in[5];   // [256, 1]
    const float* b2     = (const float*)d_in[6];   // [1]

    float* out = (float*)d_out;          // [adj_refined (1M) | h_scores (1M)]
    float* hs  = out + BN * BN;

    static int configured = 0;
    if (!configured) {
        cudaFuncSetAttribute(scorer_mma, cudaFuncAttributeMaxDynamicSharedMemorySize, SMEM_TOTAL);
        configured = 1;
    }

    prep_frag<<<64, 256>>>(W1);
    dim3 grid(BN / TJ, BN / (TI * IBG));   // (64, 128)
    scorer_mma<<<grid, 256, SMEM_TOTAL>>>(X, logits, b1, W1, W2, b2, hs);
    softmax_kernel<<<BN, 256>>>(adj, hs, out);
}

// round 14
// speedup vs baseline: 1.4621x; 1.0158x over previous
#include <cuda_runtime.h>
#include <cuda_fp16.h>
#include <math.h>
#include <stdint.h>

#define BN    1024
#define FEATN 512
#define HN    256
#define TI    4
#define TJ    16
#define KC    32       // k per chunk (2 k16 slabs)
#define NCH   16       // 512/32
#define RSB   80       // padded A row stride bytes: conflict-free ldmatrix
#define IBG   4        // i-subtiles per CTA

// ---- smem layout (bytes from 128B-aligned dynamic base) ----
#define OFF_XI   0               // 4 x 512 f32  = 8192
#define OFF_XJ   8192            // 16 x 512 f32 = 32768
#define OFF_ST   40960           // 2 A stages x 5120
#define STAGE_SZ 5120
#define OFF_EPI  51200           // float4 per col: 256 x 16 = 4096
#define OFF_RED  55296           // 64 x 4 floats = 1024
#define SMEM_TOTAL 56320

// W1[0:512] as fp16 MMA B-fragments, per-lane order (indexed by k16 slab 0..31):
// index = sc*512 + (ng*4+nt)*32 + lane ; 16B = {tile 2t: b0,b1 | tile 2t+1: b0,b1}
__device__ uint4 g_Bf[32 * 512];

__device__ __forceinline__ uint32_t smem_u32(const void* p) {
    uint32_t a;
    asm("{ .reg .u64 t; cvta.to.shared.u64 t, %1; cvt.u32.u64 %0, t; }" : "=r"(a) : "l"(p));
    return a;
}

#define LDSM_X4(r0,r1,r2,r3,addr) \
    asm volatile("ldmatrix.sync.aligned.m8n8.x4.shared.b16 {%0,%1,%2,%3}, [%4];" \
        : "=r"(r0), "=r"(r1), "=r"(r2), "=r"(r3) : "r"(addr))

#define MMAH(d, a0,a1,a2,a3, b0,b1) \
    asm volatile("mma.sync.aligned.m16n8k16.row.col.f32.f16.f16.f32 " \
        "{%0,%1,%2,%3}, {%4,%5,%6,%7}, {%8,%9}, {%0,%1,%2,%3};" \
        : "+f"((d)[0]), "+f"((d)[1]), "+f"((d)[2]), "+f"((d)[3]) \
        : "r"(a0), "r"(a1), "r"(a2), "r"(a3), "r"(b0), "r"(b1))

__device__ __forceinline__ float fast_ex2(float x) {
    float e;
    asm("ex2.approx.f32 %0, %1;" : "=f"(e) : "f"(x));
    return e;
}
__device__ __forceinline__ float fast_rcp(float x) {
    float r;
    asm("rcp.approx.f32 %0, %1;" : "=f"(r) : "f"(x));
    return r;
}
// fast sigmoid(x) = 1/(1+2^(-x*log2e))
__device__ __forceinline__ float fast_sigmoid(float x) {
    return fast_rcp(1.0f + fast_ex2(-1.4426950408889634f * x));
}

// branch-free scaled GELU body: returns x*(1+erf(x/sqrt2)); caller applies 0.5
// via the pre-scaled W2. erf via A&S 7.1.25 3-term (abs err < 2.5e-5)
__device__ __forceinline__ float gelu2_erf(float x) {
    float u = 0.70710678118654752f * x;
    float a = fabsf(u);
    float t = fast_rcp(fmaf(0.47047f, a, 1.0f));
    float p = fmaf(fmaf(0.7478556f, t, -0.0958798f), t, 0.3480242f) * t;
    float e = fast_ex2(a * a * -1.4426950408889634f);
    float erfa = fmaf(-p, e, 1.0f);
    float erfu = copysignf(erfa, u);
    return x * (1.0f + erfu);
}

// ---- prep: W1[0:512] -> fp16 B fragments in per-lane MMA order -------------
__global__ void prep_frag(const float* __restrict__ W1) {
    int idx  = blockIdx.x * 256 + threadIdx.x;    // 0..16383
    int lane = idx & 31;
    int tp   = (idx >> 5) & 15;
    int sc   = idx >> 9;                          // k16 slab 0..31
    int kg   = sc * 16 + (lane & 3) * 2;
    uint32_t e[4];
#pragma unroll
    for (int t2 = 0; t2 < 2; t2++) {
        int n = (tp * 2 + t2) * 8 + (lane >> 2);
        __half2 b0 = __floats2half2_rn(W1[kg * HN + n],       W1[(kg + 1) * HN + n]);
        __half2 b1 = __floats2half2_rn(W1[(kg + 8) * HN + n], W1[(kg + 9) * HN + n]);
        e[t2 * 2]     = *(uint32_t*)&b0;
        e[t2 * 2 + 1] = *(uint32_t*)&b1;
    }
    g_Bf[idx] = make_uint4(e[0], e[1], e[2], e[3]);
}

// ---- A build: |xi - xj| -> fp16, 8 k per thread, chunk of 32 k -------------
__device__ __forceinline__ void build_A(char* SB, uint32_t stg_off, int c, int tid) {
    int p  = tid >> 2;            // pair 0..63
    int kq = (tid & 3) * 8;       // k offset 0,8,16,24
    const float* xi = (const float*)(SB + OFF_XI) + (p >> 4) * 512 + c * KC + kq;
    const float* xj = (const float*)(SB + OFF_XJ) + (p & 15) * 512 + c * KC + kq;
    float4 xa = *(const float4*)xi, xb = *(const float4*)(xi + 4);
    float4 ya = *(const float4*)xj, yb = *(const float4*)(xj + 4);
    __half2 h0 = __float22half2_rn(make_float2(fabsf(xa.x - ya.x), fabsf(xa.y - ya.y)));
    __half2 h1 = __float22half2_rn(make_float2(fabsf(xa.z - ya.z), fabsf(xa.w - ya.w)));
    __half2 h2 = __float22half2_rn(make_float2(fabsf(xb.x - yb.x), fabsf(xb.y - yb.y)));
    __half2 h3 = __float22half2_rn(make_float2(fabsf(xb.z - yb.z), fabsf(xb.w - yb.w)));
    uint32_t off = (uint32_t)(p * RSB + kq * 2);
    *(uint4*)(SB + stg_off + off) = make_uint4(*(uint32_t*)&h0, *(uint32_t*)&h1,
                                               *(uint32_t*)&h2, *(uint32_t*)&h3);
}

// ---- main scorer: 256 thr, 4 x (M64 x N256) subtiles per CTA, 2 CTAs/SM ----
__global__ __launch_bounds__(256, 2)
void scorer_mma(const float* __restrict__ X,
                const float* __restrict__ logits,
                const float* __restrict__ b1,
                const float* __restrict__ W1,
                const float* __restrict__ W2,
                const float* __restrict__ b2,
                float* __restrict__ hs)
{
    const int ibp = blockIdx.y;          // 0..63 (groups of IBG TI-tiles)
    const int jb  = blockIdx.x;          // 0..63 (TJ=16)
    if (jb < ibp) return;                // whole CTA below diagonal

    extern __shared__ __align__(128) char SB[];
    const uint32_t sb = smem_u32(SB);

    const int tid  = threadIdx.x;
    const int wid  = tid >> 5;
    const int lane = tid & 31;
    const int j0 = jb * TJ;

    // 8 warps: 2 M-groups x 4 N-groups; warp covers M32 x N64
    const int mg = wid >> 2, ng = wid & 3;
    const int m0 = mg * 32, n0 = ng * 64;

    // ---- preload Xj rows (once) + epilogue constants (once) ----
    {
        float4* dXj = (float4*)(SB + OFF_XJ);
#pragma unroll
        for (int r = 0; r < 8; r++) {
            int idx = tid + 256 * r;              // 2048 float4
            dXj[idx] = ((const float4*)X)[(j0 + (idx >> 7)) * 128 + (idx & 127)];
        }
        float4* e = (float4*)(SB + OFF_EPI);
        e[tid] = make_float4(W1[512 * HN + tid], W1[513 * HN + tid],
                             b1[tid], 0.5f * W2[tid]);   // 0.5 folded into W2
    }

    // ---- per-thread A ldmatrix base offset / B pointer ----
    const uint32_t aBase = (uint32_t)((m0 + (lane & 7) + ((lane >> 3) & 1) * 8) * RSB
                                      + ((lane >> 4) & 1) * 16);
    const uint4* __restrict__ gB = &g_Bf[ng * 128 + lane];
    const float b2w = b2[0];

#pragma unroll 1
    for (int g = 0; g < IBG; g++) {
        const int ib = ibp * IBG + g;
        if (jb * TJ + (TJ - 1) < ib * TI) continue;
        const int i0 = ib * TI;

        // ---- load Xi rows for this subtile ----
        {
            float4* dXi = (float4*)(SB + OFF_XI);
#pragma unroll
            for (int r = 0; r < 2; r++) {
                int idx = tid + 256 * r;          // 512 float4
                dXi[idx] = ((const float4*)X)[(i0 + (idx >> 7)) * 128 + (idx & 127)];
            }
        }
        __syncthreads();

        build_A(SB, OFF_ST, 0, tid);

        float d[2][4][2][4];
#pragma unroll
        for (int a = 0; a < 2; a++)
#pragma unroll
            for (int b = 0; b < 4; b++)
#pragma unroll
                for (int cc = 0; cc < 2; cc++)
#pragma unroll
                    for (int r = 0; r < 4; r++) d[a][b][cc][r] = 0.0f;

        // ---- main K loop: 16 chunks of k32 ----
        for (int c = 0; c < NCH; c++) {
            const int s = c & 1;
            const uint32_t stg = sb + OFF_ST + s * STAGE_SZ;

            uint4 Bv0[4];
#pragma unroll
            for (int nt = 0; nt < 4; nt++)
                Bv0[nt] = __ldg(gB + (c * 2) * 512 + nt * 32);

            __syncthreads();

            uint32_t af[2][2][4];
#pragma unroll
            for (int ks = 0; ks < 2; ks++)
#pragma unroll
                for (int m2 = 0; m2 < 2; m2++) {
                    uint32_t aa = stg + aBase + m2 * (16 * RSB) + ks * 32;
                    LDSM_X4(af[ks][m2][0], af[ks][m2][1], af[ks][m2][2], af[ks][m2][3], aa);
                }

            uint4 Bv1[4];
#pragma unroll
            for (int nt = 0; nt < 4; nt++)
                Bv1[nt] = __ldg(gB + (c * 2 + 1) * 512 + nt * 32);

            if (c + 1 < NCH)
                build_A(SB, OFF_ST + (s ^ 1) * STAGE_SZ, c + 1, tid);

#pragma unroll
            for (int nt = 0; nt < 4; nt++)
#pragma unroll
                for (int m2 = 0; m2 < 2; m2++) {
                    MMAH(d[m2][nt][0], af[0][m2][0],af[0][m2][1],af[0][m2][2],af[0][m2][3],
                         Bv0[nt].x, Bv0[nt].y);
                    MMAH(d[m2][nt][1], af[0][m2][0],af[0][m2][1],af[0][m2][2],af[0][m2][3],
                         Bv0[nt].z, Bv0[nt].w);
                }
#pragma unroll
            for (int nt = 0; nt < 4; nt++)
#pragma unroll
                for (int m2 = 0; m2 < 2; m2++) {
                    MMAH(d[m2][nt][0], af[1][m2][0],af[1][m2][1],af[1][m2][2],af[1][m2][3],
                         Bv1[nt].x, Bv1[nt].y);
                    MMAH(d[m2][nt][1], af[1][m2][0],af[1][m2][1],af[1][m2][2],af[1][m2][3],
                         Bv1[nt].z, Bv1[nt].w);
                }
        }
        __syncthreads();

        // ---- epilogue ----
        float c0[4], c1[4], sacc[4];
#pragma unroll
        for (int rr = 0; rr < 4; rr++) {
            int p = m0 + (lane >> 2) + 8 * rr;
            int gi = i0 + (p >> 4), gj = j0 + (p & 15);
            float pi = fast_sigmoid(logits[gi*2] - logits[gi*2+1]);
            float pj = fast_sigmoid(logits[gj*2] - logits[gj*2+1]);
            c0[rr] = pi * pj;
            c1[rr] = (1.0f - pi) * (1.0f - pj);
            sacc[rr] = 0.0f;
        }

        const float4* epi4 = (const float4*)(SB + OFF_EPI);
#pragma unroll
        for (int nt = 0; nt < 4; nt++)
#pragma unroll
            for (int half = 0; half < 2; half++)
#pragma unroll
                for (int e = 0; e < 2; e++) {
                    int col = n0 + nt * 16 + half * 8 + (lane & 3) * 2 + e;
                    float4 w = epi4[col];
#pragma unroll
                    for (int rr = 0; rr < 4; rr++) {
                        int m2 = rr >> 1;
                        int idx = (rr & 1) * 2 + e;
                        float x = d[m2][nt][half][idx]
                                + c0[rr] * w.x + c1[rr] * w.y + w.z;
                        sacc[rr] = fmaf(gelu2_erf(x), w.w, sacc[rr]);
                    }
                }

#pragma unroll
        for (int rr = 0; rr < 4; rr++) {
            sacc[rr] += __shfl_xor_sync(0xffffffffu, sacc[rr], 1);
            sacc[rr] += __shfl_xor_sync(0xffffffffu, sacc[rr], 2);
        }
        float* red = (float*)(SB + OFF_RED);
        if ((lane & 3) == 0) {
#pragma unroll
            for (int rr = 0; rr < 4; rr++) {
                int p = m0 + (lane >> 2) + 8 * rr;
                red[p * 4 + ng] = sacc[rr];
            }
        }
        __syncthreads();

        if (tid < 64) {
            int p = tid;
            float4 r4 = *(const float4*)&red[p * 4];
            float tot = (r4.x + r4.y) + (r4.z + r4.w) + b2w;
            float sc = fast_sigmoid(tot);
            int gi = i0 + (p >> 4), gj = j0 + (p & 15);
            hs[gi * BN + gj] = sc;
            hs[gj * BN + gi] = sc;
        }
        __syncthreads();   // red/Xi safe for next subtile
    }
}

// ---------------- row softmax of adj + 5*log(hs + 1e-8) ----------------
__global__ __launch_bounds__(256)
void softmax_kernel(const float* __restrict__ adj,
                    const float* __restrict__ hs,
                    float* __restrict__ out)
{
    const int row = blockIdx.x;
    const int tid = threadIdx.x;
    __shared__ float red[256];

    float v[4];
    float mx = -3.4e38f;
#pragma unroll
    for (int u = 0; u < 4; u++) {
        int j = tid + 256 * u;
        float s = hs[row * BN + j];
        v[u] = adj[row * BN + j] + 5.0f * __logf(s + 1e-8f);
        mx = fmaxf(mx, v[u]);
    }
    red[tid] = mx;
    __syncthreads();
    for (int off = 128; off > 0; off >>= 1) {
        if (tid < off) red[tid] = fmaxf(red[tid], red[tid + off]);
        __syncthreads();
    }
    mx = red[0];
    __syncthreads();

    float sum = 0.0f;
#pragma unroll
    for (int u = 0; u < 4; u++) {
        v[u] = __expf(v[u] - mx);
        sum += v[u];
    }
    red[tid] = sum;
    __syncthreads();
    for (int off = 128; off > 0; off >>= 1) {
        if (tid < off) red[tid] += red[tid + off];
        __syncthreads();
    }
    float inv = 1.0f / red[0];
#pragma unroll
    for (int u = 0; u < 4; u++) {
        int j = tid + 256 * u;
        out[row * BN + j] = v[u] * inv;
    }
}

extern "C" void kernel_launch(void* const* d_in, const int* in_sizes, int n_in,
                              void* d_out, int out_size)
{
    const float* X      = (const float*)d_in[0];   // [1024, 512]
    const float* logits = (const float*)d_in[1];   // [1024, 2]
    const float* adj    = (const float*)d_in[2];   // [1024, 1024]
    const float* W1     = (const float*)d_in[3];   // [514, 256]
    const float* b1     = (const float*)d_in[4];   // [256]
    const float* W2     = (const float*)d_in[5];   // [256, 1]
    const float* b2     = (const float*)d_in[6];   // [1]

    float* out = (float*)d_out;          // [adj_refined (1M) | h_scores (1M)]
    float* hs  = out + BN * BN;

    static int configured = 0;
    if (!configured) {
        cudaFuncSetAttribute(scorer_mma, cudaFuncAttributeMaxDynamicSharedMemorySize, SMEM_TOTAL);
        configured = 1;
    }

    prep_frag<<<64, 256>>>(W1);
    dim3 grid(BN / TJ, BN / (TI * IBG));   // (64, 64)
    scorer_mma<<<grid, 256, SMEM_TOTAL>>>(X, logits, b1, W1, W2, b2, hs);
    softmax_kernel<<<BN, 256>>>(adj, hs, out);
}

// round 15
// speedup vs baseline: 1.5104x; 1.0330x over previous
#include <cuda_runtime.h>
#include <cuda_fp16.h>
#include <math.h>
#include <stdint.h>

#define BN    1024
#define FEATN 512
#define HN    256
#define TI    4
#define TJ    16
#define KC    32       // k per chunk (2 k16 slabs)
#define NCH   16       // 512/32
#define RSB   80       // padded A row stride bytes: conflict-free ldmatrix
#define IBG   4        // i-subtiles per CTA

// ---- smem layout (bytes from 128B-aligned dynamic base) ----
#define OFF_XI   0               // 4 x 512 f32  = 8192
#define OFF_XJ   8192            // 16 x 512 f32 = 32768
#define OFF_ST   40960           // 2 A stages x 5120
#define STAGE_SZ 5120
#define OFF_EXT  51200           // A_ext slab: 64 x 80 = 5120
#define OFF_EPI  56320           // 0.5*W2 per col: 256 x 4 = 1024
#define OFF_RED  57344           // 64 x 4 floats = 1024
#define SMEM_TOTAL 58368

// W1 as fp16 MMA B-fragments, per-lane order. Slabs 0..31 = W1[0:512];
// slab 32 = ext rows {Wc0, Wc1, b1, 0...}.
// index = sc*512 + (ng*4+nt)*32 + lane ; 16B = {tile 2t: b0,b1 | tile 2t+1: b0,b1}
__device__ uint4 g_Bf[33 * 512];

__device__ __forceinline__ uint32_t smem_u32(const void* p) {
    uint32_t a;
    asm("{ .reg .u64 t; cvta.to.shared.u64 t, %1; cvt.u32.u64 %0, t; }" : "=r"(a) : "l"(p));
    return a;
}

#define LDSM_X4(r0,r1,r2,r3,addr) \
    asm volatile("ldmatrix.sync.aligned.m8n8.x4.shared.b16 {%0,%1,%2,%3}, [%4];" \
        : "=r"(r0), "=r"(r1), "=r"(r2), "=r"(r3) : "r"(addr))

#define MMAH(d, a0,a1,a2,a3, b0,b1) \
    asm volatile("mma.sync.aligned.m16n8k16.row.col.f32.f16.f16.f32 " \
        "{%0,%1,%2,%3}, {%4,%5,%6,%7}, {%8,%9}, {%0,%1,%2,%3};" \
        : "+f"((d)[0]), "+f"((d)[1]), "+f"((d)[2]), "+f"((d)[3]) \
        : "r"(a0), "r"(a1), "r"(a2), "r"(a3), "r"(b0), "r"(b1))

__device__ __forceinline__ float fast_ex2(float x) {
    float e;
    asm("ex2.approx.f32 %0, %1;" : "=f"(e) : "f"(x));
    return e;
}
__device__ __forceinline__ float fast_rcp(float x) {
    float r;
    asm("rcp.approx.f32 %0, %1;" : "=f"(r) : "f"(x));
    return r;
}
// fast sigmoid(x) = 1/(1+2^(-x*log2e))
__device__ __forceinline__ float fast_sigmoid(float x) {
    return fast_rcp(1.0f + fast_ex2(-1.4426950408889634f * x));
}

// scaled GELU body: returns x*(1+erf(x/sqrt2)); caller applies 0.5 via the
// pre-scaled W2. erf via A&S 7.1.25 3-term, sqrt(1/2) folded into constants.
__device__ __forceinline__ float gelu2_erf(float x) {
    float a = fabsf(x);
    float t = fast_rcp(fmaf(0.33267275f, a, 1.0f));        // 0.47047/sqrt2
    float p = fmaf(fmaf(0.7478556f, t, -0.0958798f), t, 0.3480242f) * t;
    float e = fast_ex2(x * x * -0.72134752f);              // log2e/2
    float erfa = fmaf(-p, e, 1.0f);
    float erfu = copysignf(erfa, x);
    return fmaf(x, erfu, x);
}

// ---- prep: W1 -> fp16 B fragments (slabs 0..31) + ext slab 32 --------------
__global__ void prep_frag(const float* __restrict__ W1, const float* __restrict__ b1) {
    int idx  = blockIdx.x * 256 + threadIdx.x;    // 0..16895
    int lane = idx & 31;
    int tp   = (idx >> 5) & 15;
    int sc   = idx >> 9;                          // slab 0..32
    uint32_t e[4];
    if (sc < 32) {
        int kg = sc * 16 + (lane & 3) * 2;
#pragma unroll
        for (int t2 = 0; t2 < 2; t2++) {
            int n = (tp * 2 + t2) * 8 + (lane >> 2);
            __half2 b0 = __floats2half2_rn(W1[kg * HN + n],       W1[(kg + 1) * HN + n]);
            __half2 bb = __floats2half2_rn(W1[(kg + 8) * HN + n], W1[(kg + 9) * HN + n]);
            e[t2 * 2]     = *(uint32_t*)&b0;
            e[t2 * 2 + 1] = *(uint32_t*)&bb;
        }
    } else {
        // ext slab rows: 0=Wc0, 1=Wc1, 2=b1, 3..15=0
        int k0 = (lane & 3) * 2;   // 0,2,4,6
#pragma unroll
        for (int t2 = 0; t2 < 2; t2++) {
            int n = (tp * 2 + t2) * 8 + (lane >> 2);
            float v0 = (k0 == 0) ? W1[512 * HN + n] : ((k0 == 2) ? b1[n] : 0.0f);
            float v1 = (k0 == 0) ? W1[513 * HN + n] : 0.0f;
            __half2 b0 = __floats2half2_rn(v0, v1);
            e[t2 * 2]     = *(uint32_t*)&b0;
            e[t2 * 2 + 1] = 0u;    // rows 8..15 = 0
        }
    }
    g_Bf[idx] = make_uint4(e[0], e[1], e[2], e[3]);
}

// ---- A build: |xi - xj| -> fp16, 8 k per thread, chunk of 32 k -------------
__device__ __forceinline__ void build_A(char* SB, uint32_t stg_off, int c, int tid) {
    int p  = tid >> 2;            // pair 0..63
    int kq = (tid & 3) * 8;       // k offset 0,8,16,24
    const float* xi = (const float*)(SB + OFF_XI) + (p >> 4) * 512 + c * KC + kq;
    const float* xj = (const float*)(SB + OFF_XJ) + (p & 15) * 512 + c * KC + kq;
    float4 xa = *(const float4*)xi, xb = *(const float4*)(xi + 4);
    float4 ya = *(const float4*)xj, yb = *(const float4*)(xj + 4);
    __half2 h0 = __float22half2_rn(make_float2(fabsf(xa.x - ya.x), fabsf(xa.y - ya.y)));
    __half2 h1 = __float22half2_rn(make_float2(fabsf(xa.z - ya.z), fabsf(xa.w - ya.w)));
    __half2 h2 = __float22half2_rn(make_float2(fabsf(xb.x - yb.x), fabsf(xb.y - yb.y)));
    __half2 h3 = __float22half2_rn(make_float2(fabsf(xb.z - yb.z), fabsf(xb.w - yb.w)));
    uint32_t off = (uint32_t)(p * RSB + kq * 2);
    *(uint4*)(SB + stg_off + off) = make_uint4(*(uint32_t*)&h0, *(uint32_t*)&h1,
                                               *(uint32_t*)&h2, *(uint32_t*)&h3);
}

// ---- main scorer: 256 thr, 4 x (M64 x N256) subtiles per CTA, 2 CTAs/SM ----
__global__ __launch_bounds__(256, 2)
void scorer_mma(const float* __restrict__ X,
                const float* __restrict__ logits,
                const float* __restrict__ b1,
                const float* __restrict__ W1,
                const float* __restrict__ W2,
                const float* __restrict__ b2,
                float* __restrict__ hs)
{
    const int ibp = blockIdx.y;          // 0..63 (groups of IBG TI-tiles)
    const int jb  = blockIdx.x;          // 0..63 (TJ=16)
    if (jb < ibp) return;                // whole CTA below diagonal

    extern __shared__ __align__(128) char SB[];
    const uint32_t sb = smem_u32(SB);

    const int tid  = threadIdx.x;
    const int wid  = tid >> 5;
    const int lane = tid & 31;
    const int j0 = jb * TJ;

    // 8 warps: 2 M-groups x 4 N-groups; warp covers M32 x N64
    const int mg = wid >> 2, ng = wid & 3;
    const int m0 = mg * 32, n0 = ng * 64;

    // ---- preload Xj rows (once) + epilogue constant (once) ----
    {
        float4* dXj = (float4*)(SB + OFF_XJ);
#pragma unroll
        for (int r = 0; r < 8; r++) {
            int idx = tid + 256 * r;              // 2048 float4
            dXj[idx] = ((const float4*)X)[(j0 + (idx >> 7)) * 128 + (idx & 127)];
        }
        ((float*)(SB + OFF_EPI))[tid] = 0.5f * W2[tid];
    }

    // ---- per-thread A ldmatrix base offset / B pointers ----
    const uint32_t aBase = (uint32_t)((m0 + (lane & 7) + ((lane >> 3) & 1) * 8) * RSB
                                      + ((lane >> 4) & 1) * 16);
    const uint4* __restrict__ gB   = &g_Bf[ng * 128 + lane];
    const uint4* __restrict__ gBe  = &g_Bf[32 * 512 + ng * 128 + lane];
    const float b2w = b2[0];

#pragma unroll 1
    for (int g = 0; g < IBG; g++) {
        const int ib = ibp * IBG + g;
        if (jb * TJ + (TJ - 1) < ib * TI) continue;
        const int i0 = ib * TI;

        // ---- load Xi rows + build A_ext (c0, c1, 1, 0...) for this subtile ----
        {
            float4* dXi = (float4*)(SB + OFF_XI);
#pragma unroll
            for (int r = 0; r < 2; r++) {
                int idx = tid + 256 * r;          // 512 float4
                dXi[idx] = ((const float4*)X)[(i0 + (idx >> 7)) * 128 + (idx & 127)];
            }
            if (tid < 64) {
                int p = tid;
                int gi = i0 + (p >> 4), gj = j0 + (p & 15);
                float pi = fast_sigmoid(logits[gi*2] - logits[gi*2+1]);
                float pj = fast_sigmoid(logits[gj*2] - logits[gj*2+1]);
                __half2 v01 = __floats2half2_rn(pi * pj, (1.0f - pi) * (1.0f - pj));
                __half2 v23 = __floats2half2_rn(1.0f, 0.0f);
                uint32_t off = (uint32_t)(p * RSB);
                *(uint4*)(SB + OFF_EXT + off)      = make_uint4(*(uint32_t*)&v01,
                                                                *(uint32_t*)&v23, 0u, 0u);
                *(uint4*)(SB + OFF_EXT + off + 16) = make_uint4(0u, 0u, 0u, 0u);
            }
        }
        __syncthreads();

        build_A(SB, OFF_ST, 0, tid);

        float d[2][4][2][4];
#pragma unroll
        for (int a = 0; a < 2; a++)
#pragma unroll
            for (int b = 0; b < 4; b++)
#pragma unroll
                for (int cc = 0; cc < 2; cc++)
#pragma unroll
                    for (int r = 0; r < 4; r++) d[a][b][cc][r] = 0.0f;

        // ---- main K loop: 16 chunks of k32 ----
        for (int c = 0; c < NCH; c++) {
            const int s = c & 1;
            const uint32_t stg = sb + OFF_ST + s * STAGE_SZ;

            uint4 Bv0[4];
#pragma unroll
            for (int nt = 0; nt < 4; nt++)
                Bv0[nt] = __ldg(gB + (c * 2) * 512 + nt * 32);

            __syncthreads();

            uint32_t af[2][2][4];
#pragma unroll
            for (int ks = 0; ks < 2; ks++)
#pragma unroll
                for (int m2 = 0; m2 < 2; m2++) {
                    uint32_t aa = stg + aBase + m2 * (16 * RSB) + ks * 32;
                    LDSM_X4(af[ks][m2][0], af[ks][m2][1], af[ks][m2][2], af[ks][m2][3], aa);
                }

            uint4 Bv1[4];
#pragma unroll
            for (int nt = 0; nt < 4; nt++)
                Bv1[nt] = __ldg(gB + (c * 2 + 1) * 512 + nt * 32);

            if (c + 1 < NCH)
                build_A(SB, OFF_ST + (s ^ 1) * STAGE_SZ, c + 1, tid);

#pragma unroll
            for (int nt = 0; nt < 4; nt++)
#pragma unroll
                for (int m2 = 0; m2 < 2; m2++) {
                    MMAH(d[m2][nt][0], af[0][m2][0],af[0][m2][1],af[0][m2][2],af[0][m2][3],
                         Bv0[nt].x, Bv0[nt].y);
                    MMAH(d[m2][nt][1], af[0][m2][0],af[0][m2][1],af[0][m2][2],af[0][m2][3],
                         Bv0[nt].z, Bv0[nt].w);
                }
#pragma unroll
            for (int nt = 0; nt < 4; nt++)
#pragma unroll
                for (int m2 = 0; m2 < 2; m2++) {
                    MMAH(d[m2][nt][0], af[1][m2][0],af[1][m2][1],af[1][m2][2],af[1][m2][3],
                         Bv1[nt].x, Bv1[nt].y);
                    MMAH(d[m2][nt][1], af[1][m2][0],af[1][m2][1],af[1][m2][2],af[1][m2][3],
                         Bv1[nt].z, Bv1[nt].w);
                }
        }

        // ---- ext slab: label rank-2 term + bias via MMA ----
        {
            uint4 Bve[4];
#pragma unroll
            for (int nt = 0; nt < 4; nt++)
                Bve[nt] = __ldg(gBe + nt * 32);
            uint32_t afe[2][4];
#pragma unroll
            for (int m2 = 0; m2 < 2; m2++) {
                uint32_t aa = sb + OFF_EXT + aBase + m2 * (16 * RSB);
                LDSM_X4(afe[m2][0], afe[m2][1], afe[m2][2], afe[m2][3], aa);
            }
#pragma unroll
            for (int nt = 0; nt < 4; nt++)
#pragma unroll
                for (int m2 = 0; m2 < 2; m2++) {
                    MMAH(d[m2][nt][0], afe[m2][0],afe[m2][1],afe[m2][2],afe[m2][3],
                         Bve[nt].x, Bve[nt].y);
                    MMAH(d[m2][nt][1], afe[m2][0],afe[m2][1],afe[m2][2],afe[m2][3],
                         Bve[nt].z, Bve[nt].w);
                }
        }
        __syncthreads();

        // ---- epilogue: pure GELU + dot(0.5*W2) ----
        float sacc[4] = {0.0f, 0.0f, 0.0f, 0.0f};
        const float* w2s = (const float*)(SB + OFF_EPI);
#pragma unroll
        for (int nt = 0; nt < 4; nt++)
#pragma unroll
            for (int half = 0; half < 2; half++)
#pragma unroll
                for (int e = 0; e < 2; e++) {
                    int col = n0 + nt * 16 + half * 8 + (lane & 3) * 2 + e;
                    float w2v = w2s[col];
#pragma unroll
                    for (int rr = 0; rr < 4; rr++) {
                        int m2 = rr >> 1;
                        int idx = (rr & 1) * 2 + e;
                        sacc[rr] = fmaf(gelu2_erf(d[m2][nt][half][idx]), w2v, sacc[rr]);
                    }
                }

#pragma unroll
        for (int rr = 0; rr < 4; rr++) {
            sacc[rr] += __shfl_xor_sync(0xffffffffu, sacc[rr], 1);
            sacc[rr] += __shfl_xor_sync(0xffffffffu, sacc[rr], 2);
        }
        float* red = (float*)(SB + OFF_RED);
        if ((lane & 3) == 0) {
#pragma unroll
            for (int rr = 0; rr < 4; rr++) {
                int p = m0 + (lane >> 2) + 8 * rr;
                red[p * 4 + ng] = sacc[rr];
            }
        }
        __syncthreads();

        if (tid < 64) {
            int p = tid;
            float4 r4 = *(const float4*)&red[p * 4];
            float tot = (r4.x + r4.y) + (r4.z + r4.w) + b2w;
            float sc = fast_sigmoid(tot);
            int gi = i0 + (p >> 4), gj = j0 + (p & 15);
            hs[gi * BN + gj] = sc;
            hs[gj * BN + gi] = sc;
        }
        __syncthreads();   // red/Xi/ext safe for next subtile
    }
}

// ---------------- row softmax of adj + 5*log(hs + 1e-8) ----------------
__global__ __launch_bounds__(256)
void softmax_kernel(const float* __restrict__ adj,
                    const float* __restrict__ hs,
                    float* __restrict__ out)
{
    const int row = blockIdx.x;
    const int tid = threadIdx.x;
    __shared__ float red[256];

    float v[4];
    float mx = -3.4e38f;
#pragma unroll
    for (int u = 0; u < 4; u++) {
        int j = tid + 256 * u;
        float s = hs[row * BN + j];
        v[u] = adj[row * BN + j] + 5.0f * __logf(s + 1e-8f);
        mx = fmaxf(mx, v[u]);
    }
    red[tid] = mx;
    __syncthreads();
    for (int off = 128; off > 0; off >>= 1) {
        if (tid < off) red[tid] = fmaxf(red[tid], red[tid + off]);
        __syncthreads();
    }
    mx = red[0];
    __syncthreads();

    float sum = 0.0f;
#pragma unroll
    for (int u = 0; u < 4; u++) {
        v[u] = __expf(v[u] - mx);
        sum += v[u];
    }
    red[tid] = sum;
    __syncthreads();
    for (int off = 128; off > 0; off >>= 1) {
        if (tid < off) red[tid] += red[tid + off];
        __syncthreads();
    }
    float inv = 1.0f / red[0];
#pragma unroll
    for (int u = 0; u < 4; u++) {
        int j = tid + 256 * u;
        out[row * BN + j] = v[u] * inv;
    }
}

extern "C" void kernel_launch(void* const* d_in, const int* in_sizes, int n_in,
                              void* d_out, int out_size)
{
    const float* X      = (const float*)d_in[0];   // [1024, 512]
    const float* logits = (const float*)d_in[1];   // [1024, 2]
    const float* adj    = (const float*)d_in[2];   // [1024, 1024]
    const float* W1     = (const float*)d_in[3];   // [514, 256]
    const float* b1     = (const float*)d_in[4];   // [256]
    const float* W2     = (const float*)d_in[5];   // [256, 1]
    const float* b2     = (const float*)d_in[6];   // [1]

    float* out = (float*)d_out;          // [adj_refined (1M) | h_scores (1M)]
    float* hs  = out + BN * BN;

    static int configured = 0;
    if (!configured) {
        cudaFuncSetAttribute(scorer_mma, cudaFuncAttributeMaxDynamicSharedMemorySize, SMEM_TOTAL);
        configured = 1;
    }

    prep_frag<<<66, 256>>>(W1, b1);
    dim3 grid(BN / TJ, BN / (TI * IBG));   // (64, 64)
    scorer_mma<<<grid, 256, SMEM_TOTAL>>>(X, logits, b1, W1, W2, b2, hs);
    softmax_kernel<<<BN, 256>>>(adj, hs, out);
}